// round 1
// baseline (speedup 1.0000x reference)
#include <cuda_runtime.h>

#define HH 128
#define WW 128
#define HWP 16384      // HH*WW
#define CIN 256
#define OCH 256
#define BATCH 2
#define NPIX 32768     // BATCH*HWP

// -------- scratch (device globals; no allocations allowed) --------
__device__ float g_xn[(size_t)BATCH * HWP * CIN];   // x in NHWC: [b][p][c]
__device__ float g_agg[(size_t)BATCH * HWP * CIN];  // aggregated samples NHWC
__device__ float g_tmp[(size_t)BATCH * 27 * HWP];   // offset conv output (planar)
__device__ float g_w2[9 * 256 * 28];                // reorg'd offset weights [tap][c][o(pad 28)]

// ================= K1: NCHW -> NHWC transpose =================
__global__ void k_transpose(const float* __restrict__ x) {
    __shared__ float t[32][33];
    int p0 = blockIdx.x * 32;
    int c0 = blockIdx.y * 32;
    int b  = blockIdx.z;
    int tx = threadIdx.x, ty = threadIdx.y;
    const float* xb = x + (size_t)b * CIN * HWP;
#pragma unroll
    for (int i = 0; i < 32; i += 8)
        t[ty + i][tx] = xb[(size_t)(c0 + ty + i) * HWP + p0 + tx];
    __syncthreads();
    float* xn = g_xn + (size_t)b * HWP * CIN;
#pragma unroll
    for (int i = 0; i < 32; i += 8)
        xn[(size_t)(p0 + ty + i) * CIN + c0 + tx] = t[tx][ty + i];
}

// ================= K0: reorganize offset-conv weights =================
// w_off layout: [27][256][3][3]  ->  g_w2[tap][c][o], o padded to 28 (pad = 0)
__global__ void k_wreorg(const float* __restrict__ w_off) {
    int i = blockIdx.x * 256 + threadIdx.x;
    if (i >= 9 * 256 * 28) return;
    int o   = i % 28;
    int c   = (i / 28) % 256;
    int tap = i / (28 * 256);
    float v = 0.0f;
    if (o < 27) {
        int kh = tap / 3, kw = tap % 3;
        v = w_off[(((size_t)o * 256 + c) * 3 + kh) * 3 + kw];
    }
    g_w2[i] = v;
}

// ================= K2: 3x3 offset conv (27 outputs, pad 1) =================
// 1 pixel per thread. Per tap: stage weights [256][28] in shared, then
// inner loop does float4 x-loads and float4 weight LDS -> 4 FMAs per LDS.
__global__ __launch_bounds__(64) void k_offconv(const float* __restrict__ b_off) {
    __shared__ __align__(16) float sw[7168];  // 256*28
    int n = blockIdx.x * 64 + threadIdx.x;    // 512 blocks * 64 = 32768 pixels
    int b = n >> 14;
    int p = n & (HWP - 1);
    int y = p >> 7;
    int xx = p & (WW - 1);

    float acc[28];
#pragma unroll
    for (int o = 0; o < 28; ++o) acc[o] = (o < 27) ? b_off[o] : 0.0f;

    for (int tap = 0; tap < 9; ++tap) {
        __syncthreads();
        for (int i = threadIdx.x; i < 7168; i += 64) sw[i] = g_w2[tap * 7168 + i];
        __syncthreads();
        int yy = y + tap / 3 - 1;
        int xw = xx + tap % 3 - 1;
        if (yy >= 0 && yy < HH && xw >= 0 && xw < WW) {
            const float4* xrow =
                (const float4*)(g_xn + ((size_t)b * HWP + yy * WW + xw) * CIN);
#pragma unroll 2
            for (int c4 = 0; c4 < 64; ++c4) {
                float4 xv = xrow[c4];
                float xs[4] = {xv.x, xv.y, xv.z, xv.w};
#pragma unroll
                for (int cc = 0; cc < 4; ++cc) {
                    const float4* wrow = (const float4*)(sw + (c4 * 4 + cc) * 28);
                    float v = xs[cc];
#pragma unroll
                    for (int j = 0; j < 7; ++j) {
                        float4 wv = wrow[j];
                        acc[4 * j + 0] += v * wv.x;
                        acc[4 * j + 1] += v * wv.y;
                        acc[4 * j + 2] += v * wv.z;
                        acc[4 * j + 3] += v * wv.w;
                    }
                }
            }
        }
    }
    float* o0 = g_tmp + (size_t)b * 27 * HWP + p;
#pragma unroll
    for (int o = 0; o < 27; ++o) o0[(size_t)o * HWP] = acc[o];
}

// ================= K3: spatial softmax of mask planes =================
// one block per (b, k) over 16384 elements, in place on g_tmp channel 18+k
__global__ __launch_bounds__(256) void k_softmax() {
    int bi = blockIdx.x;
    int b = bi / 9, k = bi % 9;
    float* plane = g_tmp + (size_t)(b * 27 + 18 + k) * HWP;
    __shared__ float red[256];
    int tid = threadIdx.x;

    float mx = -1e30f;
    for (int i = tid; i < HWP; i += 256) mx = fmaxf(mx, plane[i]);
    red[tid] = mx;
    __syncthreads();
    for (int s = 128; s > 0; s >>= 1) {
        if (tid < s) red[tid] = fmaxf(red[tid], red[tid + s]);
        __syncthreads();
    }
    mx = red[0];
    __syncthreads();

    float sum = 0.0f;
    for (int i = tid; i < HWP; i += 256) sum += expf(plane[i] - mx);
    red[tid] = sum;
    __syncthreads();
    for (int s = 128; s > 0; s >>= 1) {
        if (tid < s) red[tid] += red[tid + s];
        __syncthreads();
    }
    float inv = 1.0f / red[0];

    for (int i = tid; i < HWP; i += 256) plane[i] = expf(plane[i] - mx) * inv;
}

// ================= K4: bilinear gather + mask + sum over K =================
// block = 4 pixels; 36 threads precompute 4 corners * 9 taps per pixel;
// then 64 threads/pixel each own 4 channels (float4 loads from NHWC x).
__global__ __launch_bounds__(256) void k_gather() {
    __shared__ int   s_off[144];  // 4 px * 9 taps * 4 corners
    __shared__ float s_w[144];
    int base = blockIdx.x * 4;
    int tid = threadIdx.x;

    if (tid < 36) {
        int pl = tid / 9, k = tid % 9;
        int n = base + pl;
        int b = n >> 14;
        int p = n & (HWP - 1);
        int y = p >> 7;
        int xx = p & (WW - 1);
        size_t tb = (size_t)b * 27 * HWP + p;
        float dy = g_tmp[tb + (size_t)(2 * k) * HWP];
        float dx = g_tmp[tb + (size_t)(2 * k + 1) * HWP];
        float m  = g_tmp[tb + (size_t)(18 + k) * HWP];
        float py = dy + (float)(k / 3 - 1 + y);
        float px = dx + (float)(k % 3 - 1 + xx);
        float fy = floorf(py), fx = floorf(px);
        int iy = (int)fy, ix = (int)fx;
        float ly = py - fy, lx = px - fx;
        float w[4];
        w[0] = (1.0f - ly) * (1.0f - lx) * m;
        w[1] = (1.0f - ly) * lx * m;
        w[2] = ly * (1.0f - lx) * m;
        w[3] = ly * lx * m;
        int idx = tid * 4;
#pragma unroll
        for (int j = 0; j < 4; ++j) {
            int yc = iy + (j >> 1);
            int xc = ix + (j & 1);
            bool v = (yc >= 0) && (yc < HH) && (xc >= 0) && (xc < WW);
            s_off[idx + j] = v ? (int)(((size_t)b * HWP + yc * WW + xc) * CIN) : -1;
            s_w[idx + j] = w[j];
        }
    }
    __syncthreads();

    int pl = tid >> 6;
    int c4 = (tid & 63) * 4;
    float4 acc = make_float4(0.f, 0.f, 0.f, 0.f);
    int sb = pl * 36;
#pragma unroll
    for (int t = 0; t < 36; ++t) {
        int off = s_off[sb + t];
        if (off >= 0) {
            float w = s_w[sb + t];
            float4 v = *(const float4*)(g_xn + off + c4);
            acc.x += w * v.x;
            acc.y += w * v.y;
            acc.z += w * v.z;
            acc.w += w * v.w;
        }
    }
    int n = base + pl;
    *(float4*)(g_agg + (size_t)n * CIN + c4) = acc;
}

// ================= K5: 1x1 projection GEMM + bias =================
// out[b,o,p] = sum_c weight[o,c] * agg[n,c] + bias[o],  n = b*HW + p
// M=256 (o), N=32768 (n), Kdim=256. 64x64x16 tiles, 4x4 microtile.
__global__ __launch_bounds__(256) void k_gemm(const float* __restrict__ Wt,
                                              const float* __restrict__ bias,
                                              float* __restrict__ out) {
    __shared__ __align__(16) float As[16][68];
    __shared__ __align__(16) float Bs[16][68];
    int m0 = blockIdx.y * 64;
    long n0 = (long)blockIdx.x * 64;
    int tid = threadIdx.x;
    int lr = tid >> 2;          // 0..63
    int lk = (tid & 3) * 4;     // 0,4,8,12
    int tx = tid & 15, ty = tid >> 4;

    float acc[4][4];
#pragma unroll
    for (int i = 0; i < 4; ++i)
#pragma unroll
        for (int j = 0; j < 4; ++j) acc[i][j] = 0.0f;

    for (int k0 = 0; k0 < CIN; k0 += 16) {
        float4 a = *(const float4*)(Wt + (size_t)(m0 + lr) * CIN + k0 + lk);
        float4 bv = *(const float4*)(g_agg + ((size_t)(n0 + lr)) * CIN + k0 + lk);
        __syncthreads();
        As[lk + 0][lr] = a.x; As[lk + 1][lr] = a.y;
        As[lk + 2][lr] = a.z; As[lk + 3][lr] = a.w;
        Bs[lk + 0][lr] = bv.x; Bs[lk + 1][lr] = bv.y;
        Bs[lk + 2][lr] = bv.z; Bs[lk + 3][lr] = bv.w;
        __syncthreads();
#pragma unroll
        for (int k = 0; k < 16; ++k) {
            float4 av = *(const float4*)&As[k][ty * 4];
            float4 bw = *(const float4*)&Bs[k][tx * 4];
            acc[0][0] += av.x * bw.x; acc[0][1] += av.x * bw.y;
            acc[0][2] += av.x * bw.z; acc[0][3] += av.x * bw.w;
            acc[1][0] += av.y * bw.x; acc[1][1] += av.y * bw.y;
            acc[1][2] += av.y * bw.z; acc[1][3] += av.y * bw.w;
            acc[2][0] += av.z * bw.x; acc[2][1] += av.z * bw.y;
            acc[2][2] += av.z * bw.z; acc[2][3] += av.z * bw.w;
            acc[3][0] += av.w * bw.x; acc[3][1] += av.w * bw.y;
            acc[3][2] += av.w * bw.z; acc[3][3] += av.w * bw.w;
        }
    }

    int b = (int)(n0 >> 14);
    int p0 = (int)(n0 & (HWP - 1));
#pragma unroll
    for (int i = 0; i < 4; ++i) {
        int m = m0 + ty * 4 + i;
        float bs = bias[m];
        float4 r;
        r.x = acc[i][0] + bs;
        r.y = acc[i][1] + bs;
        r.z = acc[i][2] + bs;
        r.w = acc[i][3] + bs;
        *(float4*)(out + ((size_t)(b * OCH + m)) * HWP + p0 + tx * 4) = r;
    }
}

// ================= launch =================
extern "C" void kernel_launch(void* const* d_in, const int* in_sizes, int n_in,
                              void* d_out, int out_size) {
    const float* x      = (const float*)d_in[0];
    const float* w_off  = (const float*)d_in[1];
    const float* b_off  = (const float*)d_in[2];
    const float* weight = (const float*)d_in[3];
    const float* bias   = (const float*)d_in[4];
    float* out = (float*)d_out;

    k_transpose<<<dim3(HWP / 32, CIN / 32, BATCH), dim3(32, 8)>>>(x);
    k_wreorg<<<(9 * 256 * 28 + 255) / 256, 256>>>(w_off);
    k_offconv<<<NPIX / 64, 64>>>(b_off);
    k_softmax<<<18, 256>>>();
    k_gather<<<NPIX / 4, 256>>>();
    k_gemm<<<dim3(NPIX / 64, OCH / 64), 256>>>(weight, bias, out);
}

// round 2
// speedup vs baseline: 1.0006x; 1.0006x over previous
#include <cuda_runtime.h>

#define HH 128
#define WW 128
#define HWP 16384      // HH*WW
#define CIN 256
#define OCH 256
#define BATCH 2
#define NPIX 32768     // BATCH*HWP

// -------- scratch (device globals; no allocations allowed) --------
__device__ float g_xn[(size_t)BATCH * HWP * CIN];   // x in NHWC: [b][p][c]
__device__ float g_agg[(size_t)BATCH * HWP * CIN];  // aggregated samples NHWC
__device__ float g_tmp[(size_t)BATCH * 27 * HWP];   // offset conv output (planar)
__device__ float g_w2[9 * 256 * 28];                // reorg'd offset weights [tap][c][o(pad 28)]

// ================= K1: NCHW -> NHWC transpose =================
__global__ void k_transpose(const float* __restrict__ x) {
    __shared__ float t[32][33];
    int p0 = blockIdx.x * 32;
    int c0 = blockIdx.y * 32;
    int b  = blockIdx.z;
    int tx = threadIdx.x, ty = threadIdx.y;
    const float* xb = x + (size_t)b * CIN * HWP;
#pragma unroll
    for (int i = 0; i < 32; i += 8)
        t[ty + i][tx] = xb[(size_t)(c0 + ty + i) * HWP + p0 + tx];
    __syncthreads();
    float* xn = g_xn + (size_t)b * HWP * CIN;
#pragma unroll
    for (int i = 0; i < 32; i += 8)
        xn[(size_t)(p0 + ty + i) * CIN + c0 + tx] = t[tx][ty + i];
}

// ================= K0: reorganize offset-conv weights =================
// w_off layout: [27][256][3][3]  ->  g_w2[tap][c][o], o padded to 28 (pad = 0)
__global__ void k_wreorg(const float* __restrict__ w_off) {
    int i = blockIdx.x * 256 + threadIdx.x;
    if (i >= 9 * 256 * 28) return;
    int o   = i % 28;
    int c   = (i / 28) % 256;
    int tap = i / (28 * 256);
    float v = 0.0f;
    if (o < 27) {
        int kh = tap / 3, kw = tap % 3;
        v = w_off[(((size_t)o * 256 + c) * 3 + kh) * 3 + kw];
    }
    g_w2[i] = v;
}

// ================= K2: 3x3 offset conv (27 outputs, pad 1) =================
// 1 pixel per thread. Per tap: stage weights [256][28] in shared, then
// inner loop does float4 x-loads and float4 weight LDS -> 4 FMAs per LDS.
__global__ __launch_bounds__(64) void k_offconv(const float* __restrict__ b_off) {
    __shared__ __align__(16) float sw[7168];  // 256*28
    int n = blockIdx.x * 64 + threadIdx.x;    // 512 blocks * 64 = 32768 pixels
    int b = n >> 14;
    int p = n & (HWP - 1);
    int y = p >> 7;
    int xx = p & (WW - 1);

    float acc[28];
#pragma unroll
    for (int o = 0; o < 28; ++o) acc[o] = (o < 27) ? b_off[o] : 0.0f;

    for (int tap = 0; tap < 9; ++tap) {
        __syncthreads();
        for (int i = threadIdx.x; i < 7168; i += 64) sw[i] = g_w2[tap * 7168 + i];
        __syncthreads();
        int yy = y + tap / 3 - 1;
        int xw = xx + tap % 3 - 1;
        if (yy >= 0 && yy < HH && xw >= 0 && xw < WW) {
            const float4* xrow =
                (const float4*)(g_xn + ((size_t)b * HWP + yy * WW + xw) * CIN);
#pragma unroll 2
            for (int c4 = 0; c4 < 64; ++c4) {
                float4 xv = xrow[c4];
                float xs[4] = {xv.x, xv.y, xv.z, xv.w};
#pragma unroll
                for (int cc = 0; cc < 4; ++cc) {
                    const float4* wrow = (const float4*)(sw + (c4 * 4 + cc) * 28);
                    float v = xs[cc];
#pragma unroll
                    for (int j = 0; j < 7; ++j) {
                        float4 wv = wrow[j];
                        acc[4 * j + 0] += v * wv.x;
                        acc[4 * j + 1] += v * wv.y;
                        acc[4 * j + 2] += v * wv.z;
                        acc[4 * j + 3] += v * wv.w;
                    }
                }
            }
        }
    }
    float* o0 = g_tmp + (size_t)b * 27 * HWP + p;
#pragma unroll
    for (int o = 0; o < 27; ++o) o0[(size_t)o * HWP] = acc[o];
}

// ================= K3: spatial softmax of mask planes =================
// one block per (b, k) over 16384 elements, in place on g_tmp channel 18+k
__global__ __launch_bounds__(256) void k_softmax() {
    int bi = blockIdx.x;
    int b = bi / 9, k = bi % 9;
    float* plane = g_tmp + (size_t)(b * 27 + 18 + k) * HWP;
    __shared__ float red[256];
    int tid = threadIdx.x;

    float mx = -1e30f;
    for (int i = tid; i < HWP; i += 256) mx = fmaxf(mx, plane[i]);
    red[tid] = mx;
    __syncthreads();
    for (int s = 128; s > 0; s >>= 1) {
        if (tid < s) red[tid] = fmaxf(red[tid], red[tid + s]);
        __syncthreads();
    }
    mx = red[0];
    __syncthreads();

    float sum = 0.0f;
    for (int i = tid; i < HWP; i += 256) sum += expf(plane[i] - mx);
    red[tid] = sum;
    __syncthreads();
    for (int s = 128; s > 0; s >>= 1) {
        if (tid < s) red[tid] += red[tid + s];
        __syncthreads();
    }
    float inv = 1.0f / red[0];

    for (int i = tid; i < HWP; i += 256) plane[i] = expf(plane[i] - mx) * inv;
}

// ================= K4: bilinear gather + mask + sum over K =================
// block = 4 pixels; 36 threads precompute 4 corners * 9 taps per pixel;
// then 64 threads/pixel each own 4 channels (float4 loads from NHWC x).
__global__ __launch_bounds__(256) void k_gather() {
    __shared__ int   s_off[144];  // 4 px * 9 taps * 4 corners
    __shared__ float s_w[144];
    int base = blockIdx.x * 4;
    int tid = threadIdx.x;

    if (tid < 36) {
        int pl = tid / 9, k = tid % 9;
        int n = base + pl;
        int b = n >> 14;
        int p = n & (HWP - 1);
        int y = p >> 7;
        int xx = p & (WW - 1);
        size_t tb = (size_t)b * 27 * HWP + p;
        float dy = g_tmp[tb + (size_t)(2 * k) * HWP];
        float dx = g_tmp[tb + (size_t)(2 * k + 1) * HWP];
        float m  = g_tmp[tb + (size_t)(18 + k) * HWP];
        float py = dy + (float)(k / 3 - 1 + y);
        float px = dx + (float)(k % 3 - 1 + xx);
        float fy = floorf(py), fx = floorf(px);
        int iy = (int)fy, ix = (int)fx;
        float ly = py - fy, lx = px - fx;
        float w[4];
        w[0] = (1.0f - ly) * (1.0f - lx) * m;
        w[1] = (1.0f - ly) * lx * m;
        w[2] = ly * (1.0f - lx) * m;
        w[3] = ly * lx * m;
        int idx = tid * 4;
#pragma unroll
        for (int j = 0; j < 4; ++j) {
            int yc = iy + (j >> 1);
            int xc = ix + (j & 1);
            bool v = (yc >= 0) && (yc < HH) && (xc >= 0) && (xc < WW);
            s_off[idx + j] = v ? (int)(((size_t)b * HWP + yc * WW + xc) * CIN) : -1;
            s_w[idx + j] = w[j];
        }
    }
    __syncthreads();

    int pl = tid >> 6;
    int c4 = (tid & 63) * 4;
    float4 acc = make_float4(0.f, 0.f, 0.f, 0.f);
    int sb = pl * 36;
#pragma unroll
    for (int t = 0; t < 36; ++t) {
        int off = s_off[sb + t];
        if (off >= 0) {
            float w = s_w[sb + t];
            float4 v = *(const float4*)(g_xn + off + c4);
            acc.x += w * v.x;
            acc.y += w * v.y;
            acc.z += w * v.z;
            acc.w += w * v.w;
        }
    }
    int n = base + pl;
    *(float4*)(g_agg + (size_t)n * CIN + c4) = acc;
}

// ================= K5: 1x1 projection GEMM + bias =================
// out[b,o,p] = sum_c weight[o,c] * agg[n,c] + bias[o],  n = b*HW + p
// M=256 (o), N=32768 (n), Kdim=256. 64x64x16 tiles, 4x4 microtile.
__global__ __launch_bounds__(256) void k_gemm(const float* __restrict__ Wt,
                                              const float* __restrict__ bias,
                                              float* __restrict__ out) {
    __shared__ __align__(16) float As[16][68];
    __shared__ __align__(16) float Bs[16][68];
    int m0 = blockIdx.y * 64;
    long n0 = (long)blockIdx.x * 64;
    int tid = threadIdx.x;
    int lr = tid >> 2;          // 0..63
    int lk = (tid & 3) * 4;     // 0,4,8,12
    int tx = tid & 15, ty = tid >> 4;

    float acc[4][4];
#pragma unroll
    for (int i = 0; i < 4; ++i)
#pragma unroll
        for (int j = 0; j < 4; ++j) acc[i][j] = 0.0f;

    for (int k0 = 0; k0 < CIN; k0 += 16) {
        float4 a = *(const float4*)(Wt + (size_t)(m0 + lr) * CIN + k0 + lk);
        float4 bv = *(const float4*)(g_agg + ((size_t)(n0 + lr)) * CIN + k0 + lk);
        __syncthreads();
        As[lk + 0][lr] = a.x; As[lk + 1][lr] = a.y;
        As[lk + 2][lr] = a.z; As[lk + 3][lr] = a.w;
        Bs[lk + 0][lr] = bv.x; Bs[lk + 1][lr] = bv.y;
        Bs[lk + 2][lr] = bv.z; Bs[lk + 3][lr] = bv.w;
        __syncthreads();
#pragma unroll
        for (int k = 0; k < 16; ++k) {
            float4 av = *(const float4*)&As[k][ty * 4];
            float4 bw = *(const float4*)&Bs[k][tx * 4];
            acc[0][0] += av.x * bw.x; acc[0][1] += av.x * bw.y;
            acc[0][2] += av.x * bw.z; acc[0][3] += av.x * bw.w;
            acc[1][0] += av.y * bw.x; acc[1][1] += av.y * bw.y;
            acc[1][2] += av.y * bw.z; acc[1][3] += av.y * bw.w;
            acc[2][0] += av.z * bw.x; acc[2][1] += av.z * bw.y;
            acc[2][2] += av.z * bw.z; acc[2][3] += av.z * bw.w;
            acc[3][0] += av.w * bw.x; acc[3][1] += av.w * bw.y;
            acc[3][2] += av.w * bw.z; acc[3][3] += av.w * bw.w;
        }
    }

    int b = (int)(n0 >> 14);
    int p0 = (int)(n0 & (HWP - 1));
#pragma unroll
    for (int i = 0; i < 4; ++i) {
        int m = m0 + ty * 4 + i;
        float bs = bias[m];
        float4 r;
        r.x = acc[i][0] + bs;
        r.y = acc[i][1] + bs;
        r.z = acc[i][2] + bs;
        r.w = acc[i][3] + bs;
        *(float4*)(out + ((size_t)(b * OCH + m)) * HWP + p0 + tx * 4) = r;
    }
}

// ================= launch =================
extern "C" void kernel_launch(void* const* d_in, const int* in_sizes, int n_in,
                              void* d_out, int out_size) {
    const float* x      = (const float*)d_in[0];
    const float* w_off  = (const float*)d_in[1];
    const float* b_off  = (const float*)d_in[2];
    const float* weight = (const float*)d_in[3];
    const float* bias   = (const float*)d_in[4];
    float* out = (float*)d_out;

    k_transpose<<<dim3(HWP / 32, CIN / 32, BATCH), dim3(32, 8)>>>(x);
    k_wreorg<<<(9 * 256 * 28 + 255) / 256, 256>>>(w_off);
    k_offconv<<<NPIX / 64, 64>>>(b_off);
    k_softmax<<<18, 256>>>();
    k_gather<<<NPIX / 4, 256>>>();
    k_gemm<<<dim3(NPIX / 64, OCH / 64), 256>>>(weight, bias, out);
}

// round 5
// speedup vs baseline: 2.8580x; 2.8564x over previous
#include <cuda_runtime.h>
#include <cuda_bf16.h>
#include <cstdint>

#define HH 128
#define WW 128
#define HWP 16384      // HH*WW
#define CIN 256
#define OCH 256
#define BATCH 2
#define NPIX 32768     // BATCH*HWP
#define LDK 40         // padded k-stride for smem tiles (conflict-free, 16B-aligned rows)

// -------- scratch (device globals) --------
__device__ __nv_bfloat16 g_xb[(size_t)NPIX * CIN];    // x in NHWC bf16
__device__ __nv_bfloat16 g_agg[(size_t)NPIX * CIN];   // aggregated samples NHWC bf16
__device__ float g_tmp[(size_t)BATCH * 27 * HWP];     // offset conv output (planar fp32)
__device__ __nv_bfloat16 g_w3[32 * 2304];             // offconv weights [o(pad32)][tap*256+c]
__device__ __nv_bfloat16 g_wproj[256 * 256];          // 1x1 weights bf16 [o][c]

// ================= mma.sync bf16 m16n8k16 =================
__device__ __forceinline__ void mma16816(float* c, uint32_t a0, uint32_t a1,
                                         uint32_t a2, uint32_t a3,
                                         uint32_t b0, uint32_t b1) {
    asm volatile(
        "mma.sync.aligned.m16n8k16.row.col.f32.bf16.bf16.f32 "
        "{%0,%1,%2,%3}, {%4,%5,%6,%7}, {%8,%9}, {%0,%1,%2,%3};\n"
        : "+f"(c[0]), "+f"(c[1]), "+f"(c[2]), "+f"(c[3])
        : "r"(a0), "r"(a1), "r"(a2), "r"(a3), "r"(b0), "r"(b1));
}

// ================= K1: NCHW -> NHWC bf16 =================
__global__ void k_transpose(const float* __restrict__ x) {
    __shared__ float t[32][33];
    int p0 = blockIdx.x * 32;
    int c0 = blockIdx.y * 32;
    int b  = blockIdx.z;
    int tx = threadIdx.x, ty = threadIdx.y;
    const float* xb = x + (size_t)b * CIN * HWP;
#pragma unroll
    for (int i = 0; i < 32; i += 8)
        t[ty + i][tx] = xb[(size_t)(c0 + ty + i) * HWP + p0 + tx];
    __syncthreads();
    __nv_bfloat16* xn = g_xb + (size_t)b * HWP * CIN;
#pragma unroll
    for (int i = 0; i < 32; i += 8)
        xn[(size_t)(p0 + ty + i) * CIN + c0 + tx] = __float2bfloat16(t[tx][ty + i]);
}

// ================= K0: weight prep (both GEMMs) =================
// g_w3[o][tap*256+c] = w_off[o][c][kh][kw] (o<27 else 0); g_wproj[o][c] = weight
__global__ void k_wprep(const float* __restrict__ w_off,
                        const float* __restrict__ weight) {
    int i = blockIdx.x * 256 + threadIdx.x;
    if (i < 32 * 2304) {
        int k = i % 2304, o = i / 2304;
        float v = 0.0f;
        if (o < 27) {
            int tap = k / 256, c = k % 256;
            v = w_off[(size_t)(o * 256 + c) * 9 + tap];
        }
        g_w3[i] = __float2bfloat16(v);
    } else {
        int j = i - 32 * 2304;
        if (j < 65536) g_wproj[j] = __float2bfloat16(weight[j]);
    }
}

// ================= K2: offset conv via implicit-GEMM bf16 mma =================
// out32[32, NPIX] = W[32, 2304] @ im2col(x). One block = one image row (128 px).
// 8 warps, each owns a 32(m) x 16(n) tile. K loop: 9 taps x 8 chunks of 32 ch.
__global__ __launch_bounds__(256) void k_offmma(const float* __restrict__ b_off) {
    __shared__ __nv_bfloat16 sA[32 * LDK];
    __shared__ __nv_bfloat16 sB[128 * LDK];
    int bid = blockIdx.x;               // 0..255
    int b = bid >> 7, y = bid & 127;
    int tid = threadIdx.x;
    int warp = tid >> 5, lane = tid & 31;
    int g = lane >> 2, tg = lane & 3;

    float acc[4][4] = {};               // [mt*2+nt][4]

    int sxx = tid >> 1;                 // B stage: pixel x (0..127)
    int scc = (tid & 1) * 16;           // B stage: channel sub-offset
    int sm  = tid >> 3;                 // A stage: row (0..31)
    int skk = (tid & 7) * 4;            // A stage: k sub-offset

    for (int chunk = 0; chunk < 72; ++chunk) {
        int tap = chunk >> 3;
        int c0  = (chunk & 7) * 32;
        int k0  = tap * 256 + c0;
        __syncthreads();
        // stage A: 32x32
        *(uint2*)&sA[sm * LDK + skk] =
            *(const uint2*)(g_w3 + (size_t)sm * 2304 + k0 + skk);
        // stage B: 128x32 (row segment of x, zero-padded at borders)
        {
            int yy = y + tap / 3 - 1;
            int sx = sxx + tap % 3 - 1;
            float4 v0 = make_float4(0.f, 0.f, 0.f, 0.f), v1 = v0;
            if (yy >= 0 && yy < HH && sx >= 0 && sx < WW) {
                const float4* src = (const float4*)(g_xb +
                    ((size_t)((b << 14) + yy * WW + sx) * CIN + c0 + scc));
                v0 = src[0];
                v1 = src[1];
            }
            *(float4*)&sB[sxx * LDK + scc]     = v0;
            *(float4*)&sB[sxx * LDK + scc + 8] = v1;
        }
        __syncthreads();
        int n0 = warp * 16;
#pragma unroll
        for (int ks = 0; ks < 2; ++ks) {
            int kk = ks * 16;
            uint32_t a[2][4];
#pragma unroll
            for (int mt = 0; mt < 2; ++mt) {
                int m = mt * 16;
                a[mt][0] = *(uint32_t*)&sA[(m + g) * LDK + kk + tg * 2];
                a[mt][1] = *(uint32_t*)&sA[(m + g + 8) * LDK + kk + tg * 2];
                a[mt][2] = *(uint32_t*)&sA[(m + g) * LDK + kk + tg * 2 + 8];
                a[mt][3] = *(uint32_t*)&sA[(m + g + 8) * LDK + kk + tg * 2 + 8];
            }
#pragma unroll
            for (int nt = 0; nt < 2; ++nt) {
                int n = n0 + nt * 8;
                uint32_t b0 = *(uint32_t*)&sB[(n + g) * LDK + kk + tg * 2];
                uint32_t b1 = *(uint32_t*)&sB[(n + g) * LDK + kk + tg * 2 + 8];
#pragma unroll
                for (int mt = 0; mt < 2; ++mt)
                    mma16816(acc[mt * 2 + nt], a[mt][0], a[mt][1], a[mt][2],
                             a[mt][3], b0, b1);
            }
        }
    }
    // epilogue: +b_off, write fp32 planes (only o < 27)
    int p0 = y * WW + warp * 16;
    float* outb = g_tmp + (size_t)b * 27 * HWP;
#pragma unroll
    for (int mt = 0; mt < 2; ++mt)
#pragma unroll
        for (int nt = 0; nt < 2; ++nt) {
            float* c = acc[mt * 2 + nt];
            int col = p0 + nt * 8 + tg * 2;
            int o1 = mt * 16 + g, o2 = o1 + 8;
            if (o1 < 27) {
                float bo = b_off[o1];
                *(float2*)&outb[(size_t)o1 * HWP + col] =
                    make_float2(c[0] + bo, c[1] + bo);
            }
            if (o2 < 27) {
                float bo = b_off[o2];
                *(float2*)&outb[(size_t)o2 * HWP + col] =
                    make_float2(c[2] + bo, c[3] + bo);
            }
        }
}

// ================= K3: spatial softmax of mask planes =================
__global__ __launch_bounds__(256) void k_softmax() {
    int bi = blockIdx.x;
    int b = bi / 9, k = bi % 9;
    float* plane = g_tmp + (size_t)(b * 27 + 18 + k) * HWP;
    __shared__ float red[256];
    int tid = threadIdx.x;

    float mx = -1e30f;
    for (int i = tid; i < HWP; i += 256) mx = fmaxf(mx, plane[i]);
    red[tid] = mx;
    __syncthreads();
    for (int s = 128; s > 0; s >>= 1) {
        if (tid < s) red[tid] = fmaxf(red[tid], red[tid + s]);
        __syncthreads();
    }
    mx = red[0];
    __syncthreads();

    float sum = 0.0f;
    for (int i = tid; i < HWP; i += 256) sum += expf(plane[i] - mx);
    red[tid] = sum;
    __syncthreads();
    for (int s = 128; s > 0; s >>= 1) {
        if (tid < s) red[tid] += red[tid + s];
        __syncthreads();
    }
    float inv = 1.0f / red[0];

    for (int i = tid; i < HWP; i += 256) plane[i] = expf(plane[i] - mx) * inv;
}

// ================= K4: bilinear gather + mask + sum over K =================
// block = 8 pixels; 72 threads precompute corners; 32 threads/pixel x 8 ch.
__global__ __launch_bounds__(256) void k_gather() {
    __shared__ int   s_off[288];
    __shared__ float s_w[288];
    int base = blockIdx.x * 8;
    int tid = threadIdx.x;

    if (tid < 72) {
        int pl = tid / 9, k = tid % 9;
        int n = base + pl;
        int b = n >> 14;
        int p = n & (HWP - 1);
        int y = p >> 7;
        int xx = p & (WW - 1);
        size_t tb = (size_t)b * 27 * HWP + p;
        float dy = g_tmp[tb + (size_t)(2 * k) * HWP];
        float dx = g_tmp[tb + (size_t)(2 * k + 1) * HWP];
        float m  = g_tmp[tb + (size_t)(18 + k) * HWP];
        float py = dy + (float)(k / 3 - 1 + y);
        float px = dx + (float)(k % 3 - 1 + xx);
        float fy = floorf(py), fx = floorf(px);
        int iy = (int)fy, ix = (int)fx;
        float ly = py - fy, lx = px - fx;
        float w[4];
        w[0] = (1.0f - ly) * (1.0f - lx) * m;
        w[1] = (1.0f - ly) * lx * m;
        w[2] = ly * (1.0f - lx) * m;
        w[3] = ly * lx * m;
        int idx = tid * 4;
#pragma unroll
        for (int j = 0; j < 4; ++j) {
            int yc = iy + (j >> 1);
            int xc = ix + (j & 1);
            bool v = (yc >= 0) && (yc < HH) && (xc >= 0) && (xc < WW);
            s_off[idx + j] = v ? (int)(((b << 14) + yc * WW + xc) * CIN) : -1;
            s_w[idx + j] = w[j];
        }
    }
    __syncthreads();

    int pl = tid >> 5;
    int c8 = (tid & 31) * 8;
    float acc[8] = {};
    int sb = pl * 36;
#pragma unroll
    for (int t = 0; t < 36; ++t) {
        int off = s_off[sb + t];
        if (off >= 0) {
            float w = s_w[sb + t];
            float4 raw = *(const float4*)(g_xb + off + c8);
            __nv_bfloat162* h = (__nv_bfloat162*)&raw;
#pragma unroll
            for (int q = 0; q < 4; ++q) {
                float2 f = __bfloat1622float2(h[q]);
                acc[2 * q]     += w * f.x;
                acc[2 * q + 1] += w * f.y;
            }
        }
    }
    int n = base + pl;
    __nv_bfloat162 outv[4];
#pragma unroll
    for (int q = 0; q < 4; ++q)
        outv[q] = __float22bfloat162_rn(make_float2(acc[2 * q], acc[2 * q + 1]));
    *(float4*)(g_agg + (size_t)n * CIN + c8) = *(float4*)outv;
}

// ================= K5: 1x1 projection GEMM (bf16 mma) + bias =================
// out[256, 32768] = Wproj[256,256] @ agg^T. Block tile 128x128, 8 warps (4m x 2n),
// warp tile 32(m) x 64(n). K chunks of 32.
__global__ __launch_bounds__(256) void k_projmma(const float* __restrict__ bias,
                                                 float* __restrict__ out) {
    __shared__ __nv_bfloat16 sA[128 * LDK];
    __shared__ __nv_bfloat16 sB[128 * LDK];
    int m0 = blockIdx.y * 128;
    int n0 = blockIdx.x * 128;
    int tid = threadIdx.x;
    int warp = tid >> 5, lane = tid & 31;
    int g = lane >> 2, tg = lane & 3;
    int wm = (warp >> 1) * 32;
    int wn = (warp & 1) * 64;

    float acc[2][8][4] = {};

    int sr = tid >> 1;
    int sk = (tid & 1) * 16;

    for (int k0 = 0; k0 < 256; k0 += 32) {
        __syncthreads();
        {
            const float4* srcA =
                (const float4*)(g_wproj + (size_t)(m0 + sr) * 256 + k0 + sk);
            *(float4*)&sA[sr * LDK + sk]     = srcA[0];
            *(float4*)&sA[sr * LDK + sk + 8] = srcA[1];
            const float4* srcB =
                (const float4*)(g_agg + (size_t)(n0 + sr) * 256 + k0 + sk);
            *(float4*)&sB[sr * LDK + sk]     = srcB[0];
            *(float4*)&sB[sr * LDK + sk + 8] = srcB[1];
        }
        __syncthreads();
#pragma unroll
        for (int ks = 0; ks < 2; ++ks) {
            int kk = ks * 16;
            uint32_t a[2][4];
#pragma unroll
            for (int mt = 0; mt < 2; ++mt) {
                int m = wm + mt * 16;
                a[mt][0] = *(uint32_t*)&sA[(m + g) * LDK + kk + tg * 2];
                a[mt][1] = *(uint32_t*)&sA[(m + g + 8) * LDK + kk + tg * 2];
                a[mt][2] = *(uint32_t*)&sA[(m + g) * LDK + kk + tg * 2 + 8];
                a[mt][3] = *(uint32_t*)&sA[(m + g + 8) * LDK + kk + tg * 2 + 8];
            }
#pragma unroll
            for (int nt = 0; nt < 8; ++nt) {
                int n = wn + nt * 8;
                uint32_t b0 = *(uint32_t*)&sB[(n + g) * LDK + kk + tg * 2];
                uint32_t b1 = *(uint32_t*)&sB[(n + g) * LDK + kk + tg * 2 + 8];
#pragma unroll
                for (int mt = 0; mt < 2; ++mt)
                    mma16816(acc[mt][nt], a[mt][0], a[mt][1], a[mt][2], a[mt][3],
                             b0, b1);
            }
        }
    }
    int b = n0 >> 14;
    int p0 = (n0 & (HWP - 1)) + wn;
#pragma unroll
    for (int mt = 0; mt < 2; ++mt) {
        int o1 = m0 + wm + mt * 16 + g;
        int o2 = o1 + 8;
        float bo1 = bias[o1], bo2 = bias[o2];
        float* r1 = out + (size_t)(b * OCH + o1) * HWP + p0;
        float* r2 = out + (size_t)(b * OCH + o2) * HWP + p0;
#pragma unroll
        for (int nt = 0; nt < 8; ++nt) {
            float* c = acc[mt][nt];
            int col = nt * 8 + tg * 2;
            *(float2*)&r1[col] = make_float2(c[0] + bo1, c[1] + bo1);
            *(float2*)&r2[col] = make_float2(c[2] + bo2, c[3] + bo2);
        }
    }
}

// ================= launch =================
extern "C" void kernel_launch(void* const* d_in, const int* in_sizes, int n_in,
                              void* d_out, int out_size) {
    const float* x      = (const float*)d_in[0];
    const float* w_off  = (const float*)d_in[1];
    const float* b_off  = (const float*)d_in[2];
    const float* weight = (const float*)d_in[3];
    const float* bias   = (const float*)d_in[4];
    float* out = (float*)d_out;

    k_transpose<<<dim3(HWP / 32, CIN / 32, BATCH), dim3(32, 8)>>>(x);
    k_wprep<<<544, 256>>>(w_off, weight);
    k_offmma<<<256, 256>>>(b_off);
    k_softmax<<<18, 256>>>();
    k_gather<<<NPIX / 8, 256>>>();
    k_projmma<<<dim3(NPIX / 128, OCH / 128), 256>>>(bias, out);
}

// round 7
// speedup vs baseline: 2.9870x; 1.0451x over previous
#include <cuda_runtime.h>
#include <cuda_bf16.h>
#include <cstdint>

#define HH 128
#define WW 128
#define HWP 16384      // HH*WW
#define CIN 256
#define OCH 256
#define BATCH 2
#define NPIX 32768     // BATCH*HWP
#define LDK 40         // padded k-stride for smem tiles

// -------- scratch (device globals) --------
__device__ __nv_bfloat16 g_xb[(size_t)NPIX * CIN];    // x in NHWC bf16
__device__ __nv_bfloat16 g_agg[(size_t)NPIX * CIN];   // aggregated samples NHWC bf16
__device__ float g_tmp[(size_t)BATCH * 27 * HWP];     // offset conv output (planar fp32)
__device__ __nv_bfloat16 g_w3[32 * 2304];             // offconv weights [o(pad32)][tap*256+c]
__device__ __nv_bfloat16 g_wproj[256 * 256];          // 1x1 weights bf16 [o][c]
__device__ float g_inv[18];                           // 1/sum(exp) per (b,k) mask plane

// ================= mma.sync bf16 m16n8k16 =================
__device__ __forceinline__ void mma16816(float* c, uint32_t a0, uint32_t a1,
                                         uint32_t a2, uint32_t a3,
                                         uint32_t b0, uint32_t b1) {
    asm volatile(
        "mma.sync.aligned.m16n8k16.row.col.f32.bf16.bf16.f32 "
        "{%0,%1,%2,%3}, {%4,%5,%6,%7}, {%8,%9}, {%0,%1,%2,%3};\n"
        : "+f"(c[0]), "+f"(c[1]), "+f"(c[2]), "+f"(c[3])
        : "r"(a0), "r"(a1), "r"(a2), "r"(a3), "r"(b0), "r"(b1));
}

// ================= K1: NCHW -> NHWC bf16 =================
__global__ void k_transpose(const float* __restrict__ x) {
    __shared__ float t[32][33];
    int p0 = blockIdx.x * 32;
    int c0 = blockIdx.y * 32;
    int b  = blockIdx.z;
    int tx = threadIdx.x, ty = threadIdx.y;
    int tid = ty * 32 + tx;
    const float* xb = x + (size_t)b * CIN * HWP;
#pragma unroll
    for (int i = 0; i < 32; i += 8)
        t[ty + i][tx] = xb[(size_t)(c0 + ty + i) * HWP + p0 + tx];
    __syncthreads();
    __nv_bfloat162* xn = (__nv_bfloat162*)(g_xb + (size_t)b * HWP * CIN);
#pragma unroll
    for (int pass = 0; pass < 2; ++pass) {
        int r  = (tid >> 4) + pass * 16;   // pixel row within tile
        int pc = tid & 15;                 // channel pair
        __nv_bfloat162 v = __floats2bfloat162_rn(t[2 * pc][r], t[2 * pc + 1][r]);
        xn[((size_t)(p0 + r) * CIN + c0) / 2 + pc] = v;
    }
}

// ================= K0: weight prep (both GEMMs) =================
__global__ void k_wprep(const float* __restrict__ w_off,
                        const float* __restrict__ weight) {
    int i = blockIdx.x * 256 + threadIdx.x;
    if (i < 32 * 2304) {
        int k = i % 2304, o = i / 2304;
        float v = 0.0f;
        if (o < 27) {
            int tap = k / 256, c = k % 256;
            v = w_off[(size_t)(o * 256 + c) * 9 + tap];
        }
        g_w3[i] = __float2bfloat16(v);
    } else {
        int j = i - 32 * 2304;
        if (j < 65536) g_wproj[j] = __float2bfloat16(weight[j]);
    }
}

// ================= K2: offset conv, implicit-GEMM bf16 mma, pipelined =================
// out32[32, NPIX] = W[32, 2304] @ im2col(x). One block = one image row (128 px).
// Double-buffered smem + register prefetch: ONE bar.sync per chunk.
__global__ __launch_bounds__(256) void k_offmma(const float* __restrict__ b_off) {
    __shared__ __nv_bfloat16 sA[2][32 * LDK];
    __shared__ __nv_bfloat16 sB[2][128 * LDK];
    int bid = blockIdx.x;               // 0..255
    int b = bid >> 7, y = bid & 127;
    int tid = threadIdx.x;
    int warp = tid >> 5, lane = tid & 31;
    int g = lane >> 2, tg = lane & 3;

    float acc[4][4] = {};

    int sxx = tid >> 1;                 // B stage: pixel x (0..127)
    int scc = (tid & 1) * 16;           // B stage: channel sub-offset
    int sm  = tid >> 3;                 // A stage: row (0..31)
    int skk = (tid & 7) * 4;            // A stage: k sub-offset

    uint2 ra;
    float4 rb0, rb1;
    auto load = [&](int chunk) {
        int tap = chunk >> 3;
        int c0  = (chunk & 7) * 32;
        int k0  = tap * 256 + c0;
        ra = *(const uint2*)(g_w3 + (size_t)sm * 2304 + k0 + skk);
        int yy = y + tap / 3 - 1;
        int sx = sxx + tap % 3 - 1;
        rb0 = make_float4(0.f, 0.f, 0.f, 0.f);
        rb1 = rb0;
        if (yy >= 0 && yy < HH && sx >= 0 && sx < WW) {
            const float4* src = (const float4*)(g_xb +
                ((size_t)((b << 14) + yy * WW + sx) * CIN + c0 + scc));
            rb0 = src[0];
            rb1 = src[1];
        }
    };
    auto store = [&](int buf) {
        *(uint2*)&sA[buf][sm * LDK + skk]       = ra;
        *(float4*)&sB[buf][sxx * LDK + scc]     = rb0;
        *(float4*)&sB[buf][sxx * LDK + scc + 8] = rb1;
    };

    load(0);
    store(0);
    __syncthreads();

    int n0 = warp * 16;
    for (int c = 0; c < 72; ++c) {
        int buf = c & 1;
        if (c < 71) load(c + 1);
#pragma unroll
        for (int ks = 0; ks < 2; ++ks) {
            int kk = ks * 16;
            uint32_t a[2][4];
#pragma unroll
            for (int mt = 0; mt < 2; ++mt) {
                int m = mt * 16;
                a[mt][0] = *(uint32_t*)&sA[buf][(m + g) * LDK + kk + tg * 2];
                a[mt][1] = *(uint32_t*)&sA[buf][(m + g + 8) * LDK + kk + tg * 2];
                a[mt][2] = *(uint32_t*)&sA[buf][(m + g) * LDK + kk + tg * 2 + 8];
                a[mt][3] = *(uint32_t*)&sA[buf][(m + g + 8) * LDK + kk + tg * 2 + 8];
            }
#pragma unroll
            for (int nt = 0; nt < 2; ++nt) {
                int n = n0 + nt * 8;
                uint32_t b0 = *(uint32_t*)&sB[buf][(n + g) * LDK + kk + tg * 2];
                uint32_t b1 = *(uint32_t*)&sB[buf][(n + g) * LDK + kk + tg * 2 + 8];
#pragma unroll
                for (int mt = 0; mt < 2; ++mt)
                    mma16816(acc[mt * 2 + nt], a[mt][0], a[mt][1], a[mt][2],
                             a[mt][3], b0, b1);
            }
        }
        if (c < 71) store(buf ^ 1);
        __syncthreads();
    }

    // epilogue: +b_off, write fp32 planes (only o < 27)
    int p0 = y * WW + warp * 16;
    float* outb = g_tmp + (size_t)b * 27 * HWP;
#pragma unroll
    for (int mt = 0; mt < 2; ++mt)
#pragma unroll
        for (int nt = 0; nt < 2; ++nt) {
            float* c = acc[mt * 2 + nt];
            int col = p0 + nt * 8 + tg * 2;
            int o1 = mt * 16 + g, o2 = o1 + 8;
            if (o1 < 27) {
                float bo = b_off[o1];
                *(float2*)&outb[(size_t)o1 * HWP + col] =
                    make_float2(c[0] + bo, c[1] + bo);
            }
            if (o2 < 27) {
                float bo = b_off[o2];
                *(float2*)&outb[(size_t)o2 * HWP + col] =
                    make_float2(c[2] + bo, c[3] + bo);
            }
        }
}

// ================= K3: sum-of-exp per mask plane (no max-subtract; |v|~<5) ===
__global__ __launch_bounds__(1024) void k_sumexp() {
    int bi = blockIdx.x;  // 0..17
    const float* plane =
        g_tmp + (size_t)((bi / 9) * 27 + 18 + (bi % 9)) * HWP;
    __shared__ float red[1024];
    int tid = threadIdx.x;
    float s = 0.0f;
    for (int i = tid; i < HWP; i += 1024) s += expf(plane[i]);
    red[tid] = s;
    __syncthreads();
    for (int st = 512; st > 0; st >>= 1) {
        if (tid < st) red[tid] += red[tid + st];
        __syncthreads();
    }
    if (tid == 0) g_inv[bi] = 1.0f / red[0];
}

// ================= K4: bilinear gather + mask + sum over K =================
// block = 16 pixels, 512 threads; 144 threads precompute corners (mask inline);
// then 32 threads/pixel, 8 channels each.
__global__ __launch_bounds__(512) void k_gather() {
    __shared__ int   s_off[576];
    __shared__ float s_w[576];
    int base = blockIdx.x * 16;
    int tid = threadIdx.x;

    if (tid < 144) {
        int pl = tid / 9, k = tid % 9;
        int n = base + pl;
        int b = n >> 14;
        int p = n & (HWP - 1);
        int y = p >> 7;
        int xx = p & (WW - 1);
        size_t tb = (size_t)b * 27 * HWP + p;
        float dy = g_tmp[tb + (size_t)(2 * k) * HWP];
        float dx = g_tmp[tb + (size_t)(2 * k + 1) * HWP];
        float mv = g_tmp[tb + (size_t)(18 + k) * HWP];
        float m  = expf(mv) * g_inv[b * 9 + k];
        float py = dy + (float)(k / 3 - 1 + y);
        float px = dx + (float)(k % 3 - 1 + xx);
        float fy = floorf(py), fx = floorf(px);
        int iy = (int)fy, ix = (int)fx;
        float ly = py - fy, lx = px - fx;
        float w[4];
        w[0] = (1.0f - ly) * (1.0f - lx) * m;
        w[1] = (1.0f - ly) * lx * m;
        w[2] = ly * (1.0f - lx) * m;
        w[3] = ly * lx * m;
        int idx = tid * 4;
#pragma unroll
        for (int j = 0; j < 4; ++j) {
            int yc = iy + (j >> 1);
            int xc = ix + (j & 1);
            bool v = (yc >= 0) && (yc < HH) && (xc >= 0) && (xc < WW);
            s_off[idx + j] = v ? (int)(((b << 14) + yc * WW + xc) * CIN) : -1;
            s_w[idx + j] = w[j];
        }
    }
    __syncthreads();

    int pl = tid >> 5;
    int c8 = (tid & 31) * 8;
    float acc[8] = {};
    int sb = pl * 36;
#pragma unroll
    for (int t = 0; t < 36; ++t) {
        int off = s_off[sb + t];
        if (off >= 0) {
            float w = s_w[sb + t];
            float4 raw = *(const float4*)(g_xb + off + c8);
            __nv_bfloat162* h = (__nv_bfloat162*)&raw;
#pragma unroll
            for (int q = 0; q < 4; ++q) {
                float2 f = __bfloat1622float2(h[q]);
                acc[2 * q]     += w * f.x;
                acc[2 * q + 1] += w * f.y;
            }
        }
    }
    int n = base + pl;
    __nv_bfloat162 outv[4];
#pragma unroll
    for (int q = 0; q < 4; ++q)
        outv[q] = __float22bfloat162_rn(make_float2(acc[2 * q], acc[2 * q + 1]));
    *(float4*)(g_agg + (size_t)n * CIN + c8) = *(float4*)outv;
}

// ================= K5: 1x1 projection GEMM (bf16 mma) + bias, pipelined =====
__global__ __launch_bounds__(256) void k_projmma(const float* __restrict__ bias,
                                                 float* __restrict__ out) {
    __shared__ __nv_bfloat16 sA[2][128 * LDK];
    __shared__ __nv_bfloat16 sB[2][128 * LDK];
    int m0 = blockIdx.y * 128;
    int n0 = blockIdx.x * 128;
    int tid = threadIdx.x;
    int warp = tid >> 5, lane = tid & 31;
    int g = lane >> 2, tg = lane & 3;
    int wm = (warp >> 1) * 32;
    int wn = (warp & 1) * 64;

    float acc[2][8][4] = {};

    int sr = tid >> 1;
    int sk = (tid & 1) * 16;

    float4 ra0, ra1, rb0, rb1;
    auto load = [&](int chunk) {
        int k0 = chunk * 32;
        const float4* srcA =
            (const float4*)(g_wproj + (size_t)(m0 + sr) * 256 + k0 + sk);
        ra0 = srcA[0];
        ra1 = srcA[1];
        const float4* srcB =
            (const float4*)(g_agg + (size_t)(n0 + sr) * 256 + k0 + sk);
        rb0 = srcB[0];
        rb1 = srcB[1];
    };
    auto store = [&](int buf) {
        *(float4*)&sA[buf][sr * LDK + sk]     = ra0;
        *(float4*)&sA[buf][sr * LDK + sk + 8] = ra1;
        *(float4*)&sB[buf][sr * LDK + sk]     = rb0;
        *(float4*)&sB[buf][sr * LDK + sk + 8] = rb1;
    };

    load(0);
    store(0);
    __syncthreads();

    for (int c = 0; c < 8; ++c) {
        int buf = c & 1;
        if (c < 7) load(c + 1);
#pragma unroll
        for (int ks = 0; ks < 2; ++ks) {
            int kk = ks * 16;
            uint32_t a[2][4];
#pragma unroll
            for (int mt = 0; mt < 2; ++mt) {
                int m = wm + mt * 16;
                a[mt][0] = *(uint32_t*)&sA[buf][(m + g) * LDK + kk + tg * 2];
                a[mt][1] = *(uint32_t*)&sA[buf][(m + g + 8) * LDK + kk + tg * 2];
                a[mt][2] = *(uint32_t*)&sA[buf][(m + g) * LDK + kk + tg * 2 + 8];
                a[mt][3] = *(uint32_t*)&sA[buf][(m + g + 8) * LDK + kk + tg * 2 + 8];
            }
#pragma unroll
            for (int nt = 0; nt < 8; ++nt) {
                int n = wn + nt * 8;
                uint32_t b0 = *(uint32_t*)&sB[buf][(n + g) * LDK + kk + tg * 2];
                uint32_t b1 = *(uint32_t*)&sB[buf][(n + g) * LDK + kk + tg * 2 + 8];
#pragma unroll
                for (int mt = 0; mt < 2; ++mt)
                    mma16816(acc[mt][nt], a[mt][0], a[mt][1], a[mt][2], a[mt][3],
                             b0, b1);
            }
        }
        if (c < 7) store(buf ^ 1);
        __syncthreads();
    }

    int b = n0 >> 14;
    int p0 = (n0 & (HWP - 1)) + wn;
#pragma unroll
    for (int mt = 0; mt < 2; ++mt) {
        int o1 = m0 + wm + mt * 16 + g;
        int o2 = o1 + 8;
        float bo1 = bias[o1], bo2 = bias[o2];
        float* r1 = out + (size_t)(b * OCH + o1) * HWP + p0;
        float* r2 = out + (size_t)(b * OCH + o2) * HWP + p0;
#pragma unroll
        for (int nt = 0; nt < 8; ++nt) {
            float* c = acc[mt][nt];
            int col = nt * 8 + tg * 2;
            *(float2*)&r1[col] = make_float2(c[0] + bo1, c[1] + bo1);
            *(float2*)&r2[col] = make_float2(c[2] + bo2, c[3] + bo2);
        }
    }
}

// ================= launch =================
extern "C" void kernel_launch(void* const* d_in, const int* in_sizes, int n_in,
                              void* d_out, int out_size) {
    const float* x      = (const float*)d_in[0];
    const float* w_off  = (const float*)d_in[1];
    const float* b_off  = (const float*)d_in[2];
    const float* weight = (const float*)d_in[3];
    const float* bias   = (const float*)d_in[4];
    float* out = (float*)d_out;

    k_transpose<<<dim3(HWP / 32, CIN / 32, BATCH), dim3(32, 8)>>>(x);
    k_wprep<<<544, 256>>>(w_off, weight);
    k_offmma<<<256, 256>>>(b_off);
    k_sumexp<<<18, 1024>>>();
    k_gather<<<NPIX / 16, 512>>>();
    k_projmma<<<dim3(NPIX / 128, OCH / 128), 256>>>(bias, out);
}